// round 8
// baseline (speedup 1.0000x reference)
#include <cuda_runtime.h>
#include <cuda_bf16.h>

#define N_NODES 100000
#define N_EDGES 1600000
#define F_IN    128
#define HID     128
#define N_CLS   40

// ---------------- scratch (static device globals; no allocation) ----------------
__device__ int   g_deg[N_NODES];
__device__ int   g_rowptr[N_NODES + 1];
__device__ int   g_cursor[N_NODES];
__device__ float g_dinv[N_NODES];
__device__ int   g_col[N_EDGES];
__device__ float g_Hs [(size_t)N_NODES * HID];   // (X@W1) * dinv[row]
__device__ float g_H1 [(size_t)N_NODES * HID];   // relu(agg1 + b1)
__device__ float g_Hs2[(size_t)N_NODES * N_CLS]; // (H1@W2) * dinv[row]

// ---------------- fp32x2 packed-math helpers ----------------
__device__ __forceinline__ unsigned long long pack2(float x) {
    unsigned long long r;
    asm("mov.b64 %0, {%1, %1};" : "=l"(r) : "f"(x));
    return r;
}
__device__ __forceinline__ void fma2(unsigned long long& d, unsigned long long a,
                                     unsigned long long b) {
    asm("fma.rn.f32x2 %0, %1, %2, %0;" : "+l"(d) : "l"(a), "l"(b));
}
__device__ __forceinline__ unsigned long long mul2(unsigned long long a,
                                                   unsigned long long b) {
    unsigned long long r;
    asm("mul.rn.f32x2 %0, %1, %2;" : "=l"(r) : "l"(a), "l"(b));
    return r;
}

// ---------------- CSR build ----------------
__global__ void init_deg_kernel() {
    int i = blockIdx.x * blockDim.x + threadIdx.x;
    if (i < N_NODES) g_deg[i] = 1;              // self loop
}

__global__ void count_deg_kernel(const int* __restrict__ ei) {
    int e = blockIdx.x * blockDim.x + threadIdx.x;
    if (e < N_EDGES) atomicAdd(&g_deg[ei[N_EDGES + e]], 1);
}

// single-block exclusive scan of (deg-1) -> rowptr, cursor; also dinv = rsqrt(deg)
__global__ void scan_kernel() {
    __shared__ int ss[1024];
    const int CHUNK = (N_NODES + 1023) / 1024;  // 98
    int t = threadIdx.x;
    int beg = t * CHUNK;
    int end = beg + CHUNK < N_NODES ? beg + CHUNK : N_NODES;
    int local = 0;
    for (int i = beg; i < end; i++) local += g_deg[i] - 1;
    ss[t] = local;
    __syncthreads();
    for (int off = 1; off < 1024; off <<= 1) {
        int v = (t >= off) ? ss[t - off] : 0;
        __syncthreads();
        ss[t] += v;
        __syncthreads();
    }
    int run = ss[t] - local;                    // exclusive prefix
    for (int i = beg; i < end; i++) {
        g_rowptr[i] = run;
        g_cursor[i] = run;
        g_dinv[i]   = rsqrtf((float)g_deg[i]);
        run += g_deg[i] - 1;
    }
    if (t == 1023) g_rowptr[N_NODES] = ss[1023];
}

__global__ void fill_csr_kernel(const int* __restrict__ ei) {
    int e = blockIdx.x * blockDim.x + threadIdx.x;
    if (e >= N_EDGES) return;
    int src = ei[e];
    int dst = ei[N_EDGES + e];
    int p = atomicAdd(&g_cursor[dst], 1);
    g_col[p] = src;
}

// ---------------- GEMM1: Hs = (X @ W1) * dinv[row]  (100000x128 @ 128x128) -----
// block = 128 threads, tile 64 rows x 128 cols; thread computes 4 rows x 16 cols
__global__ void __launch_bounds__(128) gemm1_kernel(const float* __restrict__ X,
                                                    const float* __restrict__ W) {
    __shared__ float sX[64][33];     // padded: conflict-free column reads
    __shared__ float sW[32][128];
    int t  = threadIdx.x;
    int rg = t & 15;                 // row group (4 rows)
    int cg = t >> 4;                 // col group (16 cols)
    int row0 = blockIdx.x * 64;

    unsigned long long acc[4][8];
#pragma unroll
    for (int i = 0; i < 4; i++)
#pragma unroll
        for (int j = 0; j < 8; j++) acc[i][j] = 0ull;

    for (int k0 = 0; k0 < F_IN; k0 += 32) {
#pragma unroll
        for (int i = 0; i < 4; i++) {        // X tile 64x32 = 512 float4
            int f = t + i * 128;
            int r = f >> 3, c = (f & 7) << 2;
            float4 v = make_float4(0.f, 0.f, 0.f, 0.f);
            if (row0 + r < N_NODES)
                v = *(const float4*)(X + (size_t)(row0 + r) * F_IN + k0 + c);
            sX[r][c] = v.x; sX[r][c + 1] = v.y; sX[r][c + 2] = v.z; sX[r][c + 3] = v.w;
        }
#pragma unroll
        for (int i = 0; i < 8; i++) {        // W tile 32x128 = 1024 float4
            int f = t + i * 128;
            int r = f >> 5, c = (f & 31) << 2;
            *(float4*)&sW[r][c] = *(const float4*)(W + (size_t)(k0 + r) * HID + c);
        }
        __syncthreads();
#pragma unroll 4
        for (int kk = 0; kk < 32; kk++) {
            unsigned long long w[8];
            const ulonglong2* wp = (const ulonglong2*)&sW[kk][cg * 16];
            ulonglong2 wv;
            wv = wp[0]; w[0] = wv.x; w[1] = wv.y;
            wv = wp[1]; w[2] = wv.x; w[3] = wv.y;
            wv = wp[2]; w[4] = wv.x; w[5] = wv.y;
            wv = wp[3]; w[6] = wv.x; w[7] = wv.y;
#pragma unroll
            for (int i = 0; i < 4; i++) {
                unsigned long long x2 = pack2(sX[rg * 4 + i][kk]);
#pragma unroll
                for (int j = 0; j < 8; j++) fma2(acc[i][j], x2, w[j]);
            }
        }
        __syncthreads();
    }
#pragma unroll
    for (int i = 0; i < 4; i++) {
        int row = row0 + rg * 4 + i;
        if (row < N_NODES) {
            unsigned long long d2 = pack2(g_dinv[row]);
#pragma unroll
            for (int j = 0; j < 8; j++)
                *(unsigned long long*)&g_Hs[(size_t)row * HID + cg * 16 + j * 2] =
                    mul2(acc[i][j], d2);
        }
    }
}

// ---------------- agg1: H1 = relu(dinv * (Hs[self] + sum Hs[col]) + b1) --------
// one warp per node, lane owns 4 consecutive features (float4)
__global__ void agg1_kernel(const float* __restrict__ b1) {
    int warp = threadIdx.x >> 5;
    int lane = threadIdx.x & 31;
    int node = blockIdx.x * 4 + warp;
    if (node >= N_NODES) return;
    int beg = g_rowptr[node], end = g_rowptr[node + 1];
    const float4* Hs4 = (const float4*)g_Hs;
    float4 s = Hs4[(size_t)node * 32 + lane];        // self loop
    int e = beg;
    for (; e + 4 <= end; e += 4) {
        int i0 = g_col[e], i1 = g_col[e + 1], i2 = g_col[e + 2], i3 = g_col[e + 3];
        float4 a0 = Hs4[(size_t)i0 * 32 + lane];
        float4 a1 = Hs4[(size_t)i1 * 32 + lane];
        float4 a2 = Hs4[(size_t)i2 * 32 + lane];
        float4 a3 = Hs4[(size_t)i3 * 32 + lane];
        s.x += (a0.x + a1.x) + (a2.x + a3.x);
        s.y += (a0.y + a1.y) + (a2.y + a3.y);
        s.z += (a0.z + a1.z) + (a2.z + a3.z);
        s.w += (a0.w + a1.w) + (a2.w + a3.w);
    }
    for (; e < end; e++) {
        float4 a = Hs4[(size_t)g_col[e] * 32 + lane];
        s.x += a.x; s.y += a.y; s.z += a.z; s.w += a.w;
    }
    float dv = g_dinv[node];
    float4 b = ((const float4*)b1)[lane];
    float4 o;
    o.x = fmaxf(fmaf(dv, s.x, b.x), 0.f);
    o.y = fmaxf(fmaf(dv, s.y, b.y), 0.f);
    o.z = fmaxf(fmaf(dv, s.z, b.z), 0.f);
    o.w = fmaxf(fmaf(dv, s.w, b.w), 0.f);
    ((float4*)g_H1)[(size_t)node * 32 + lane] = o;
}

// ---------------- GEMM2: Hs2 = (H1 @ W2) * dinv[row]  (100000x128 @ 128x40) ----
// one row per thread; W2 staged in shared
__global__ void __launch_bounds__(256) gemm2_kernel(const float* __restrict__ W2) {
    __shared__ float sW2[HID * N_CLS];   // 128*40 floats = 20 KB
    int t = threadIdx.x;
#pragma unroll
    for (int i = 0; i < 5; i++) {        // 1280 float4
        int f = t + i * 256;
        *(float4*)&sW2[f * 4] = *(const float4*)(W2 + f * 4);
    }
    __syncthreads();
    int row = blockIdx.x * 256 + t;
    if (row >= N_NODES) return;

    unsigned long long acc[20];
#pragma unroll
    for (int j = 0; j < 20; j++) acc[j] = 0ull;

    const float4* xr = (const float4*)(g_H1 + (size_t)row * HID);
#pragma unroll 2
    for (int k4 = 0; k4 < HID / 4; k4++) {
        float4 xv = xr[k4];
        float xs[4] = {xv.x, xv.y, xv.z, xv.w};
#pragma unroll
        for (int kc = 0; kc < 4; kc++) {
            unsigned long long x2 = pack2(xs[kc]);
            const ulonglong2* wp = (const ulonglong2*)&sW2[(k4 * 4 + kc) * N_CLS];
#pragma unroll
            for (int j = 0; j < 10; j++) {
                ulonglong2 wv = wp[j];
                fma2(acc[2 * j],     x2, wv.x);
                fma2(acc[2 * j + 1], x2, wv.y);
            }
        }
    }
    unsigned long long d2 = pack2(g_dinv[row]);
#pragma unroll
    for (int j = 0; j < 20; j++)
        *(unsigned long long*)&g_Hs2[(size_t)row * N_CLS + j * 2] = mul2(acc[j], d2);
}

// ---------------- agg2: out = dinv * (Hs2[self] + sum Hs2[col]) + b2 -----------
// one warp per node, lanes 0..19 own 2 features each (float2)
__global__ void agg2_kernel(const float* __restrict__ b2, float* __restrict__ out) {
    int warp = threadIdx.x >> 5;
    int lane = threadIdx.x & 31;
    int node = blockIdx.x * 8 + warp;
    if (node >= N_NODES || lane >= 20) return;
    int beg = g_rowptr[node], end = g_rowptr[node + 1];
    const float2* H2 = (const float2*)g_Hs2;
    float2 s = H2[(size_t)node * 20 + lane];          // self loop
    int e = beg;
    for (; e + 4 <= end; e += 4) {
        int i0 = g_col[e], i1 = g_col[e + 1], i2 = g_col[e + 2], i3 = g_col[e + 3];
        float2 a0 = H2[(size_t)i0 * 20 + lane];
        float2 a1 = H2[(size_t)i1 * 20 + lane];
        float2 a2 = H2[(size_t)i2 * 20 + lane];
        float2 a3 = H2[(size_t)i3 * 20 + lane];
        s.x += (a0.x + a1.x) + (a2.x + a3.x);
        s.y += (a0.y + a1.y) + (a2.y + a3.y);
    }
    for (; e < end; e++) {
        float2 a = H2[(size_t)g_col[e] * 20 + lane];
        s.x += a.x; s.y += a.y;
    }
    float dv = g_dinv[node];
    out[(size_t)node * N_CLS + lane * 2]     = fmaf(dv, s.x, b2[lane * 2]);
    out[(size_t)node * N_CLS + lane * 2 + 1] = fmaf(dv, s.y, b2[lane * 2 + 1]);
}

// ---------------- launch ----------------
extern "C" void kernel_launch(void* const* d_in, const int* in_sizes, int n_in,
                              void* d_out, int out_size) {
    const float* x  = (const float*)d_in[0];
    const int*   ei = (const int*)  d_in[1];
    const float* W1 = (const float*)d_in[2];
    const float* b1 = (const float*)d_in[3];
    const float* W2 = (const float*)d_in[4];
    const float* b2 = (const float*)d_in[5];
    float* out = (float*)d_out;
    (void)in_sizes; (void)n_in; (void)out_size;

    init_deg_kernel <<<(N_NODES + 255) / 256, 256>>>();
    count_deg_kernel<<<(N_EDGES + 255) / 256, 256>>>(ei);
    scan_kernel     <<<1, 1024>>>();
    fill_csr_kernel <<<(N_EDGES + 255) / 256, 256>>>(ei);
    gemm1_kernel    <<<(N_NODES + 63) / 64, 128>>>(x, W1);
    agg1_kernel     <<<(N_NODES + 3) / 4, 128>>>(b1);
    gemm2_kernel    <<<(N_NODES + 255) / 256, 256>>>(W2);
    agg2_kernel     <<<(N_NODES + 7) / 8, 256>>>(b2, out);
}

// round 9
// speedup vs baseline: 1.7037x; 1.7037x over previous
#include <cuda_runtime.h>
#include <cuda_bf16.h>

#define N_NODES 100000
#define N_EDGES 1600000
#define F_IN    128
#define HID     128
#define N_CLS   40
#define NBLK_SCAN 98          // ceil(100000/1024)
#define GEMM1_BLOCKS 1563     // ceil(100000/64)
#define COUNT_BLOCKS 12500    // 1.6M / 128

// ---------------- scratch (static device globals; zero-initialized) ------------
__device__ int   g_cnt[N_NODES];        // edge counts; RESET to 0 each call
__device__ int   g_rowptr[N_NODES + 1];
__device__ int   g_cursor[N_NODES];
__device__ float g_dinv[N_NODES];
__device__ int   g_bsum[NBLK_SCAN];
__device__ int   g_col[N_EDGES];
__device__ float g_H  [(size_t)N_NODES * HID];    // X@W1 (unscaled)
__device__ float g_H1 [(size_t)N_NODES * HID];    // relu(agg1 + b1)
__device__ float g_Hs2[(size_t)N_NODES * N_CLS];  // (H1@W2) * dinv[row]

// ---------------- fp32x2 packed-math helpers ----------------
__device__ __forceinline__ unsigned long long pack2(float x) {
    unsigned long long r;
    asm("mov.b64 %0, {%1, %1};" : "=l"(r) : "f"(x));
    return r;
}
__device__ __forceinline__ void fma2(unsigned long long& d, unsigned long long a,
                                     unsigned long long b) {
    asm("fma.rn.f32x2 %0, %1, %2, %0;" : "+l"(d) : "l"(a), "l"(b));
}
__device__ __forceinline__ unsigned long long mul2(unsigned long long a,
                                                   unsigned long long b) {
    unsigned long long r;
    asm("mul.rn.f32x2 %0, %1, %2;" : "=l"(r) : "l"(a), "l"(b));
    return r;
}

// ============ fat kernel: degree count (8/9 of blocks) ∥ GEMM1 (1/9) ===========
// GEMM1: H = X @ W1, 64 rows x 128 cols per block, thread = 4 rows x 16 cols
__global__ void __launch_bounds__(128) fat_kernel(const int* __restrict__ ei,
                                                  const float* __restrict__ X,
                                                  const float* __restrict__ W) {
    __shared__ float sX[64][33];
    __shared__ float sW[32][128];
    int bid = blockIdx.x;
    int r9  = bid % 9;

    if (r9 != 4) {
        // ---- degree count path ----
        int cid = (bid / 9) * 8 + (r9 > 4 ? r9 - 1 : r9);
        if (cid < COUNT_BLOCKS) {
            int e = cid * 128 + threadIdx.x;
            atomicAdd(&g_cnt[ei[N_EDGES + e]], 1);
        }
        return;
    }

    // ---- GEMM1 path ----
    int g = bid / 9;
    if (g >= GEMM1_BLOCKS) return;
    int t  = threadIdx.x;
    int rg = t & 15;
    int cg = t >> 4;
    int row0 = g * 64;

    unsigned long long acc[4][8];
#pragma unroll
    for (int i = 0; i < 4; i++)
#pragma unroll
        for (int j = 0; j < 8; j++) acc[i][j] = 0ull;

    for (int k0 = 0; k0 < F_IN; k0 += 32) {
#pragma unroll
        for (int i = 0; i < 4; i++) {
            int f = t + i * 128;
            int r = f >> 3, c = (f & 7) << 2;
            float4 v = make_float4(0.f, 0.f, 0.f, 0.f);
            if (row0 + r < N_NODES)
                v = *(const float4*)(X + (size_t)(row0 + r) * F_IN + k0 + c);
            sX[r][c] = v.x; sX[r][c + 1] = v.y; sX[r][c + 2] = v.z; sX[r][c + 3] = v.w;
        }
#pragma unroll
        for (int i = 0; i < 8; i++) {
            int f = t + i * 128;
            int r = f >> 5, c = (f & 31) << 2;
            *(float4*)&sW[r][c] = *(const float4*)(W + (size_t)(k0 + r) * HID + c);
        }
        __syncthreads();
#pragma unroll 4
        for (int kk = 0; kk < 32; kk++) {
            unsigned long long w[8];
            const ulonglong2* wp = (const ulonglong2*)&sW[kk][cg * 16];
            ulonglong2 wv;
            wv = wp[0]; w[0] = wv.x; w[1] = wv.y;
            wv = wp[1]; w[2] = wv.x; w[3] = wv.y;
            wv = wp[2]; w[4] = wv.x; w[5] = wv.y;
            wv = wp[3]; w[6] = wv.x; w[7] = wv.y;
#pragma unroll
            for (int i = 0; i < 4; i++) {
                unsigned long long x2 = pack2(sX[rg * 4 + i][kk]);
#pragma unroll
                for (int j = 0; j < 8; j++) fma2(acc[i][j], x2, w[j]);
            }
        }
        __syncthreads();
    }
#pragma unroll
    for (int i = 0; i < 4; i++) {
        int row = row0 + rg * 4 + i;
        if (row < N_NODES) {
#pragma unroll
            for (int j = 0; j < 8; j++)
                *(unsigned long long*)&g_H[(size_t)row * HID + cg * 16 + j * 2] =
                    acc[i][j];
        }
    }
}

// ============ coalesced 2-phase scan ==========================================
// phase 1: per-1024-segment sum of g_cnt
__global__ void __launch_bounds__(256) scan_reduce_kernel() {
    int b = blockIdx.x, t = threadIdx.x;
    int base = b * 1024;
    int s = 0;
#pragma unroll
    for (int k = 0; k < 4; k++) {
        int i = base + t + k * 256;
        if (i < N_NODES) s += g_cnt[i];
    }
#pragma unroll
    for (int o = 16; o; o >>= 1) s += __shfl_down_sync(0xffffffffu, s, o);
    __shared__ int ws[8];
    if ((t & 31) == 0) ws[t >> 5] = s;
    __syncthreads();
    if (t < 8) {
        int v = ws[t];
#pragma unroll
        for (int o = 4; o; o >>= 1) v += __shfl_down_sync(0xffu, v, o);
        if (t == 0) g_bsum[b] = v;
    }
}

// phase 2: block-local exclusive scan + segment offset; writes rowptr/cursor/dinv
// and resets g_cnt back to zero (so every call starts from a clean histogram)
__global__ void __launch_bounds__(1024) scan_dist_kernel() {
    __shared__ int sd[1024];
    __shared__ int sb[NBLK_SCAN];
    __shared__ int soff;
    int b = blockIdx.x, t = threadIdx.x;
    if (t < NBLK_SCAN) sb[t] = g_bsum[t];
    __syncthreads();
    if (t == 0) {
        int o = 0;
        for (int j = 0; j < b; j++) o += sb[j];
        soff = o;
    }
    int i = b * 1024 + t;
    int cnt = (i < N_NODES) ? g_cnt[i] : 0;
    sd[t] = cnt;
    __syncthreads();
    for (int o = 1; o < 1024; o <<= 1) {
        int v = (t >= o) ? sd[t - o] : 0;
        __syncthreads();
        sd[t] += v;
        __syncthreads();
    }
    int incl = sd[t];
    if (i < N_NODES) {
        int rp = soff + incl - cnt;
        g_rowptr[i] = rp;
        g_cursor[i] = rp;
        g_dinv[i]   = rsqrtf((float)(cnt + 1));   // +1 self loop
        g_cnt[i]    = 0;                           // reset for next call
        if (i == N_NODES - 1) g_rowptr[N_NODES] = soff + incl;
    }
}

__global__ void fill_csr_kernel(const int* __restrict__ ei) {
    int e = blockIdx.x * blockDim.x + threadIdx.x;
    if (e >= N_EDGES) return;
    int src = ei[e];
    int dst = ei[N_EDGES + e];
    int p = atomicAdd(&g_cursor[dst], 1);
    g_col[p] = src;
}

// ============ agg1: H1 = relu(dinv_d * (H[d]*dinv_d + sum H[s]*dinv_s) + b1) ===
__global__ void agg1_kernel(const float* __restrict__ b1) {
    int warp = threadIdx.x >> 5;
    int lane = threadIdx.x & 31;
    int node = blockIdx.x * 4 + warp;
    if (node >= N_NODES) return;
    int beg = g_rowptr[node], end = g_rowptr[node + 1];
    const float4* H4 = (const float4*)g_H;
    float dvn = g_dinv[node];
    float4 sv = H4[(size_t)node * 32 + lane];          // self loop
    float4 s;
    s.x = sv.x * dvn; s.y = sv.y * dvn; s.z = sv.z * dvn; s.w = sv.w * dvn;
    int e = beg;
    for (; e + 4 <= end; e += 4) {
        int i0 = g_col[e], i1 = g_col[e + 1], i2 = g_col[e + 2], i3 = g_col[e + 3];
        float d0 = g_dinv[i0], d1 = g_dinv[i1], d2 = g_dinv[i2], d3 = g_dinv[i3];
        float4 a0 = H4[(size_t)i0 * 32 + lane];
        float4 a1 = H4[(size_t)i1 * 32 + lane];
        float4 a2 = H4[(size_t)i2 * 32 + lane];
        float4 a3 = H4[(size_t)i3 * 32 + lane];
        s.x += (a0.x * d0 + a1.x * d1) + (a2.x * d2 + a3.x * d3);
        s.y += (a0.y * d0 + a1.y * d1) + (a2.y * d2 + a3.y * d3);
        s.z += (a0.z * d0 + a1.z * d1) + (a2.z * d2 + a3.z * d3);
        s.w += (a0.w * d0 + a1.w * d1) + (a2.w * d2 + a3.w * d3);
    }
    for (; e < end; e++) {
        int ic = g_col[e];
        float dc = g_dinv[ic];
        float4 a = H4[(size_t)ic * 32 + lane];
        s.x += a.x * dc; s.y += a.y * dc; s.z += a.z * dc; s.w += a.w * dc;
    }
    float4 b = ((const float4*)b1)[lane];
    float4 o;
    o.x = fmaxf(fmaf(dvn, s.x, b.x), 0.f);
    o.y = fmaxf(fmaf(dvn, s.y, b.y), 0.f);
    o.z = fmaxf(fmaf(dvn, s.z, b.z), 0.f);
    o.w = fmaxf(fmaf(dvn, s.w, b.w), 0.f);
    ((float4*)g_H1)[(size_t)node * 32 + lane] = o;
}

// ============ GEMM2: Hs2 = (H1 @ W2) * dinv[row] ===============================
__global__ void __launch_bounds__(256) gemm2_kernel(const float* __restrict__ W2) {
    __shared__ float sW2[HID * N_CLS];
    int t = threadIdx.x;
#pragma unroll
    for (int i = 0; i < 5; i++) {
        int f = t + i * 256;
        *(float4*)&sW2[f * 4] = *(const float4*)(W2 + f * 4);
    }
    __syncthreads();
    int row = blockIdx.x * 256 + t;
    if (row >= N_NODES) return;

    unsigned long long acc[20];
#pragma unroll
    for (int j = 0; j < 20; j++) acc[j] = 0ull;

    const float4* xr = (const float4*)(g_H1 + (size_t)row * HID);
#pragma unroll 2
    for (int k4 = 0; k4 < HID / 4; k4++) {
        float4 xv = xr[k4];
        float xs[4] = {xv.x, xv.y, xv.z, xv.w};
#pragma unroll
        for (int kc = 0; kc < 4; kc++) {
            unsigned long long x2 = pack2(xs[kc]);
            const ulonglong2* wp = (const ulonglong2*)&sW2[(k4 * 4 + kc) * N_CLS];
#pragma unroll
            for (int j = 0; j < 10; j++) {
                ulonglong2 wv = wp[j];
                fma2(acc[2 * j],     x2, wv.x);
                fma2(acc[2 * j + 1], x2, wv.y);
            }
        }
    }
    unsigned long long d2 = pack2(g_dinv[row]);
#pragma unroll
    for (int j = 0; j < 20; j++)
        *(unsigned long long*)&g_Hs2[(size_t)row * N_CLS + j * 2] = mul2(acc[j], d2);
}

// ============ agg2: out = dinv * (Hs2[self] + sum Hs2[col]) + b2 ===============
__global__ void agg2_kernel(const float* __restrict__ b2, float* __restrict__ out) {
    int warp = threadIdx.x >> 5;
    int lane = threadIdx.x & 31;
    int node = blockIdx.x * 8 + warp;
    if (node >= N_NODES || lane >= 20) return;
    int beg = g_rowptr[node], end = g_rowptr[node + 1];
    const float2* H2 = (const float2*)g_Hs2;
    float2 s = H2[(size_t)node * 20 + lane];
    int e = beg;
    for (; e + 4 <= end; e += 4) {
        int i0 = g_col[e], i1 = g_col[e + 1], i2 = g_col[e + 2], i3 = g_col[e + 3];
        float2 a0 = H2[(size_t)i0 * 20 + lane];
        float2 a1 = H2[(size_t)i1 * 20 + lane];
        float2 a2 = H2[(size_t)i2 * 20 + lane];
        float2 a3 = H2[(size_t)i3 * 20 + lane];
        s.x += (a0.x + a1.x) + (a2.x + a3.x);
        s.y += (a0.y + a1.y) + (a2.y + a3.y);
    }
    for (; e < end; e++) {
        float2 a = H2[(size_t)g_col[e] * 20 + lane];
        s.x += a.x; s.y += a.y;
    }
    float dv = g_dinv[node];
    out[(size_t)node * N_CLS + lane * 2]     = fmaf(dv, s.x, b2[lane * 2]);
    out[(size_t)node * N_CLS + lane * 2 + 1] = fmaf(dv, s.y, b2[lane * 2 + 1]);
}

// ---------------- launch ----------------
extern "C" void kernel_launch(void* const* d_in, const int* in_sizes, int n_in,
                              void* d_out, int out_size) {
    const float* x  = (const float*)d_in[0];
    const int*   ei = (const int*)  d_in[1];
    const float* W1 = (const float*)d_in[2];
    const float* b1 = (const float*)d_in[3];
    const float* W2 = (const float*)d_in[4];
    const float* b2 = (const float*)d_in[5];
    float* out = (float*)d_out;
    (void)in_sizes; (void)n_in; (void)out_size;

    fat_kernel       <<<GEMM1_BLOCKS * 9, 128>>>(ei, x, W1);  // count ∥ GEMM1
    scan_reduce_kernel<<<NBLK_SCAN, 256>>>();
    scan_dist_kernel  <<<NBLK_SCAN, 1024>>>();
    fill_csr_kernel   <<<(N_EDGES + 255) / 256, 256>>>(ei);
    agg1_kernel       <<<(N_NODES + 3) / 4, 128>>>(b1);
    gemm2_kernel      <<<(N_NODES + 255) / 256, 256>>>(W2);
    agg2_kernel       <<<(N_NODES + 7) / 8, 256>>>(b2, out);
}

// round 10
// speedup vs baseline: 1.8401x; 1.0801x over previous
#include <cuda_runtime.h>
#include <cuda_fp16.h>

#define N_NODES 100000
#define N_EDGES 1600000
#define F_IN    128
#define HID     128
#define N_CLS   40
#define NBLK_SCAN 98
#define G1A_BLOCKS 782        // rows 0..50047
#define G1B_BLOCKS 781        // rows 50048..99999
#define COUNT_BLOCKS 12500    // 1.6M / 128

// ---------------- scratch (static device globals; zero-initialized) ------------
__device__ int    g_cnt[N_NODES];
__device__ int    g_rowptr[N_NODES + 1];
__device__ int    g_cursor[N_NODES];
__device__ float  g_dinv[N_NODES];
__device__ int    g_bsum[NBLK_SCAN];
__device__ int    g_col[N_EDGES];
__device__ __half g_H  [(size_t)N_NODES * HID];    // X@W1 (unscaled, fp16)
__device__ float  g_H1 [(size_t)N_NODES * HID];    // relu(agg1 + b1), fp32
__device__ __half g_Hs2[(size_t)N_NODES * N_CLS];  // (H1@W2)*dinv[row], fp16

// ---------------- fp32x2 packed-math helpers ----------------
__device__ __forceinline__ unsigned long long pack2(float x) {
    unsigned long long r;
    asm("mov.b64 %0, {%1, %1};" : "=l"(r) : "f"(x));
    return r;
}
__device__ __forceinline__ void fma2(unsigned long long& d, unsigned long long a,
                                     unsigned long long b) {
    asm("fma.rn.f32x2 %0, %1, %2, %0;" : "+l"(d) : "l"(a), "l"(b));
}
__device__ __forceinline__ unsigned long long mul2(unsigned long long a,
                                                   unsigned long long b) {
    unsigned long long r;
    asm("mul.rn.f32x2 %0, %1, %2;" : "=l"(r) : "l"(a), "l"(b));
    return r;
}
__device__ __forceinline__ void unpack2(unsigned long long v, float& lo, float& hi) {
    asm("mov.b64 {%0, %1}, %2;" : "=f"(lo), "=f"(hi) : "l"(v));
}

// ---------------- GEMM1 body: 64 rows x 128 cols per block ---------------------
__device__ __forceinline__ void gemm1_body(const float* __restrict__ X,
                                           const float* __restrict__ W,
                                           int row0,
                                           float (&sX)[64][33], float (&sW)[32][128]) {
    int t  = threadIdx.x;
    int rg = t & 15;
    int cg = t >> 4;

    unsigned long long acc[4][8];
#pragma unroll
    for (int i = 0; i < 4; i++)
#pragma unroll
        for (int j = 0; j < 8; j++) acc[i][j] = 0ull;

    for (int k0 = 0; k0 < F_IN; k0 += 32) {
#pragma unroll
        for (int i = 0; i < 4; i++) {
            int f = t + i * 128;
            int r = f >> 3, c = (f & 7) << 2;
            float4 v = make_float4(0.f, 0.f, 0.f, 0.f);
            if (row0 + r < N_NODES)
                v = *(const float4*)(X + (size_t)(row0 + r) * F_IN + k0 + c);
            sX[r][c] = v.x; sX[r][c + 1] = v.y; sX[r][c + 2] = v.z; sX[r][c + 3] = v.w;
        }
#pragma unroll
        for (int i = 0; i < 8; i++) {
            int f = t + i * 128;
            int r = f >> 5, c = (f & 31) << 2;
            *(float4*)&sW[r][c] = *(const float4*)(W + (size_t)(k0 + r) * HID + c);
        }
        __syncthreads();
#pragma unroll 4
        for (int kk = 0; kk < 32; kk++) {
            unsigned long long w[8];
            const ulonglong2* wp = (const ulonglong2*)&sW[kk][cg * 16];
            ulonglong2 wv;
            wv = wp[0]; w[0] = wv.x; w[1] = wv.y;
            wv = wp[1]; w[2] = wv.x; w[3] = wv.y;
            wv = wp[2]; w[4] = wv.x; w[5] = wv.y;
            wv = wp[3]; w[6] = wv.x; w[7] = wv.y;
#pragma unroll
            for (int i = 0; i < 4; i++) {
                unsigned long long x2 = pack2(sX[rg * 4 + i][kk]);
#pragma unroll
                for (int j = 0; j < 8; j++) fma2(acc[i][j], x2, w[j]);
            }
        }
        __syncthreads();
    }
    // epilogue: fp32x2 -> half2, packed 16B stores
#pragma unroll
    for (int i = 0; i < 4; i++) {
        int row = row0 + rg * 4 + i;
        if (row < N_NODES) {
            uint4 pk[2];
            unsigned* pw = (unsigned*)pk;
#pragma unroll
            for (int j = 0; j < 8; j++) {
                float lo, hi;
                unpack2(acc[i][j], lo, hi);
                __half2 h = __floats2half2_rn(lo, hi);
                pw[j] = *(unsigned*)&h;
            }
            uint4* dst = (uint4*)(g_H + (size_t)row * HID + cg * 16);
            dst[0] = pk[0]; dst[1] = pk[1];
        }
    }
}

// ============ fat1: degree count (16/17 slots) ∥ GEMM1 rows [0, 50048) =========
__global__ void __launch_bounds__(128) fat1_kernel(const int* __restrict__ ei,
                                                   const float* __restrict__ X,
                                                   const float* __restrict__ W) {
    __shared__ float sX[64][33];
    __shared__ float sW[32][128];
    int bid = blockIdx.x;
    int r17 = bid % 17;
    if (r17 != 8) {
        int cid = (bid / 17) * 16 + (r17 > 8 ? r17 - 1 : r17);
        if (cid < COUNT_BLOCKS) {
            int e = cid * 128 + threadIdx.x;
            atomicAdd(&g_cnt[ei[N_EDGES + e]], 1);
        }
        return;
    }
    int g = bid / 17;
    if (g >= G1A_BLOCKS) return;
    gemm1_body(X, W, g * 64, sX, sW);
}

// ============ fat2: CSR fill (16/17 slots) ∥ GEMM1 rows [50048, 100000) ========
__global__ void __launch_bounds__(128) fat2_kernel(const int* __restrict__ ei,
                                                   const float* __restrict__ X,
                                                   const float* __restrict__ W) {
    __shared__ float sX[64][33];
    __shared__ float sW[32][128];
    int bid = blockIdx.x;
    int r17 = bid % 17;
    if (r17 != 8) {
        int cid = (bid / 17) * 16 + (r17 > 8 ? r17 - 1 : r17);
        if (cid < COUNT_BLOCKS) {
            int e = cid * 128 + threadIdx.x;
            int src = ei[e];
            int dst = ei[N_EDGES + e];
            int p = atomicAdd(&g_cursor[dst], 1);
            g_col[p] = src;
        }
        return;
    }
    int g = bid / 17;
    if (g >= G1B_BLOCKS) return;
    gemm1_body(X, W, 50048 + g * 64, sX, sW);
}

// ============ coalesced 2-phase scan ==========================================
__global__ void __launch_bounds__(256) scan_reduce_kernel() {
    int b = blockIdx.x, t = threadIdx.x;
    int base = b * 1024;
    int s = 0;
#pragma unroll
    for (int k = 0; k < 4; k++) {
        int i = base + t + k * 256;
        if (i < N_NODES) s += g_cnt[i];
    }
#pragma unroll
    for (int o = 16; o; o >>= 1) s += __shfl_down_sync(0xffffffffu, s, o);
    __shared__ int ws[8];
    if ((t & 31) == 0) ws[t >> 5] = s;
    __syncthreads();
    if (t < 8) {
        int v = ws[t];
#pragma unroll
        for (int o = 4; o; o >>= 1) v += __shfl_down_sync(0xffu, v, o);
        if (t == 0) g_bsum[b] = v;
    }
}

__global__ void __launch_bounds__(1024) scan_dist_kernel() {
    __shared__ int sd[1024];
    __shared__ int sb[NBLK_SCAN];
    __shared__ int soff;
    int b = blockIdx.x, t = threadIdx.x;
    if (t < NBLK_SCAN) sb[t] = g_bsum[t];
    __syncthreads();
    if (t == 0) {
        int o = 0;
        for (int j = 0; j < b; j++) o += sb[j];
        soff = o;
    }
    int i = b * 1024 + t;
    int cnt = (i < N_NODES) ? g_cnt[i] : 0;
    sd[t] = cnt;
    __syncthreads();
    for (int o = 1; o < 1024; o <<= 1) {
        int v = (t >= o) ? sd[t - o] : 0;
        __syncthreads();
        sd[t] += v;
        __syncthreads();
    }
    int incl = sd[t];
    if (i < N_NODES) {
        int rp = soff + incl - cnt;
        g_rowptr[i] = rp;
        g_cursor[i] = rp;
        g_dinv[i]   = rsqrtf((float)(cnt + 1));
        g_cnt[i]    = 0;
        if (i == N_NODES - 1) g_rowptr[N_NODES] = soff + incl;
    }
}

// ============ agg1: H1 = relu(dinv_d*(H[d]*dinv_d + sum H[s]*dinv_s) + b1) =====
// warp per node, lane owns 4 features = one uint2 (2x half2) per gather
__global__ void agg1_kernel(const float* __restrict__ b1) {
    int warp = threadIdx.x >> 5;
    int lane = threadIdx.x & 31;
    int node = blockIdx.x * 4 + warp;
    if (node >= N_NODES) return;
    int beg = g_rowptr[node], end = g_rowptr[node + 1];
    const uint2* Hp = (const uint2*)g_H;       // 32 uint2 per row
    float dvn = g_dinv[node];

    uint2 us = Hp[(size_t)node * 32 + lane];
    __half2* hs = (__half2*)&us;
    float2 f0 = __half22float2(hs[0]);
    float2 f1 = __half22float2(hs[1]);
    float4 s;
    s.x = f0.x * dvn; s.y = f0.y * dvn; s.z = f1.x * dvn; s.w = f1.y * dvn;

    int e = beg;
    for (; e + 4 <= end; e += 4) {
        int i0 = g_col[e], i1 = g_col[e + 1], i2 = g_col[e + 2], i3 = g_col[e + 3];
        float d0 = g_dinv[i0], d1 = g_dinv[i1], d2 = g_dinv[i2], d3 = g_dinv[i3];
        uint2 u0 = Hp[(size_t)i0 * 32 + lane];
        uint2 u1 = Hp[(size_t)i1 * 32 + lane];
        uint2 u2 = Hp[(size_t)i2 * 32 + lane];
        uint2 u3 = Hp[(size_t)i3 * 32 + lane];
        __half2* h0 = (__half2*)&u0; __half2* h1 = (__half2*)&u1;
        __half2* h2 = (__half2*)&u2; __half2* h3 = (__half2*)&u3;
        float2 a0 = __half22float2(h0[0]), b0 = __half22float2(h0[1]);
        float2 a1 = __half22float2(h1[0]), c1 = __half22float2(h1[1]);
        float2 a2 = __half22float2(h2[0]), c2 = __half22float2(h2[1]);
        float2 a3 = __half22float2(h3[0]), c3 = __half22float2(h3[1]);
        s.x += (a0.x * d0 + a1.x * d1) + (a2.x * d2 + a3.x * d3);
        s.y += (a0.y * d0 + a1.y * d1) + (a2.y * d2 + a3.y * d3);
        s.z += (b0.x * d0 + c1.x * d1) + (c2.x * d2 + c3.x * d3);
        s.w += (b0.y * d0 + c1.y * d1) + (c2.y * d2 + c3.y * d3);
    }
    for (; e < end; e++) {
        int ic = g_col[e];
        float dc = g_dinv[ic];
        uint2 u = Hp[(size_t)ic * 32 + lane];
        __half2* h = (__half2*)&u;
        float2 a = __half22float2(h[0]);
        float2 b = __half22float2(h[1]);
        s.x += a.x * dc; s.y += a.y * dc; s.z += b.x * dc; s.w += b.y * dc;
    }
    float4 bb = ((const float4*)b1)[lane];
    float4 o;
    o.x = fmaxf(fmaf(dvn, s.x, bb.x), 0.f);
    o.y = fmaxf(fmaf(dvn, s.y, bb.y), 0.f);
    o.z = fmaxf(fmaf(dvn, s.z, bb.z), 0.f);
    o.w = fmaxf(fmaf(dvn, s.w, bb.w), 0.f);
    ((float4*)g_H1)[(size_t)node * 32 + lane] = o;
}

// ============ GEMM2: Hs2 = (H1 @ W2)*dinv[row], fp16 out =======================
// block = 256 threads / 256 rows; thread = 4 strided rows x 10 cols; smem-staged
__global__ void __launch_bounds__(256) gemm2_kernel(const float* __restrict__ W2) {
    __shared__ float sH[256 * 33];    // [row][kk], pad 33: conflict-free
    __shared__ float sW[32 * 40];     // K-chunk of W2
    int t = threadIdx.x;
    int rg = t & 63;                  // base row within block
    int cg = t >> 6;                  // 4 col groups x 10 cols
    int row0 = blockIdx.x * 256;

    unsigned long long acc[4][5];
#pragma unroll
    for (int i = 0; i < 4; i++)
#pragma unroll
        for (int j = 0; j < 5; j++) acc[i][j] = 0ull;

    for (int k0 = 0; k0 < HID; k0 += 32) {
#pragma unroll
        for (int i = 0; i < 8; i++) {         // H1 tile 256x32 = 2048 float4
            int idx = t + i * 256;
            int r = idx >> 3, c4 = idx & 7;
            float4 v = make_float4(0.f, 0.f, 0.f, 0.f);
            if (row0 + r < N_NODES)
                v = *(const float4*)(g_H1 + (size_t)(row0 + r) * HID + k0 + c4 * 4);
            float* d = &sH[r * 33 + c4 * 4];
            d[0] = v.x; d[1] = v.y; d[2] = v.z; d[3] = v.w;
        }
#pragma unroll
        for (int i = 0; i < 2; i++) {         // W2 chunk 32x40 = 320 float4
            int idx = t + i * 256;
            if (idx < 320)
                *(float4*)&sW[idx * 4] = *(const float4*)(W2 + (size_t)k0 * N_CLS + idx * 4);
        }
        __syncthreads();
#pragma unroll 4
        for (int kk = 0; kk < 32; kk++) {
            const unsigned long long* wp =
                (const unsigned long long*)&sW[kk * 40 + cg * 10];
            unsigned long long w0 = wp[0], w1 = wp[1], w2 = wp[2], w3 = wp[3], w4 = wp[4];
#pragma unroll
            for (int i = 0; i < 4; i++) {
                unsigned long long x2 = pack2(sH[(rg + 64 * i) * 33 + kk]);
                fma2(acc[i][0], x2, w0);
                fma2(acc[i][1], x2, w1);
                fma2(acc[i][2], x2, w2);
                fma2(acc[i][3], x2, w3);
                fma2(acc[i][4], x2, w4);
            }
        }
        __syncthreads();
    }
#pragma unroll
    for (int i = 0; i < 4; i++) {
        int row = row0 + rg + 64 * i;
        if (row < N_NODES) {
            unsigned long long d2 = pack2(g_dinv[row]);
            __half2* dst = (__half2*)(g_Hs2 + (size_t)row * N_CLS + cg * 10);
#pragma unroll
            for (int j = 0; j < 5; j++) {
                float lo, hi;
                unpack2(mul2(acc[i][j], d2), lo, hi);
                dst[j] = __floats2half2_rn(lo, hi);
            }
        }
    }
}

// ============ agg2: out = dinv*(Hs2[self] + sum Hs2[col]) + b2 =================
// warp per node, lanes 0..19 own one half2 (2 features)
__global__ void agg2_kernel(const float* __restrict__ b2, float* __restrict__ out) {
    int warp = threadIdx.x >> 5;
    int lane = threadIdx.x & 31;
    int node = blockIdx.x * 8 + warp;
    if (node >= N_NODES || lane >= 20) return;
    int beg = g_rowptr[node], end = g_rowptr[node + 1];
    const __half2* H2 = (const __half2*)g_Hs2;   // 20 half2 per row
    float2 s = __half22float2(H2[(size_t)node * 20 + lane]);
    int e = beg;
    for (; e + 4 <= end; e += 4) {
        int i0 = g_col[e], i1 = g_col[e + 1], i2 = g_col[e + 2], i3 = g_col[e + 3];
        float2 a0 = __half22float2(H2[(size_t)i0 * 20 + lane]);
        float2 a1 = __half22float2(H2[(size_t)i1 * 20 + lane]);
        float2 a2 = __half22float2(H2[(size_t)i2 * 20 + lane]);
        float2 a3 = __half22float2(H2[(size_t)i3 * 20 + lane]);
        s.x += (a0.x + a1.x) + (a2.x + a3.x);
        s.y += (a0.y + a1.y) + (a2.y + a3.y);
    }
    for (; e < end; e++) {
        float2 a = __half22float2(H2[(size_t)g_col[e] * 20 + lane]);
        s.x += a.x; s.y += a.y;
    }
    float dv = g_dinv[node];
    out[(size_t)node * N_CLS + lane * 2]     = fmaf(dv, s.x, b2[lane * 2]);
    out[(size_t)node * N_CLS + lane * 2 + 1] = fmaf(dv, s.y, b2[lane * 2 + 1]);
}

// ---------------- launch ----------------
extern "C" void kernel_launch(void* const* d_in, const int* in_sizes, int n_in,
                              void* d_out, int out_size) {
    const float* x  = (const float*)d_in[0];
    const int*   ei = (const int*)  d_in[1];
    const float* W1 = (const float*)d_in[2];
    const float* b1 = (const float*)d_in[3];
    const float* W2 = (const float*)d_in[4];
    const float* b2 = (const float*)d_in[5];
    float* out = (float*)d_out;
    (void)in_sizes; (void)n_in; (void)out_size;

    fat1_kernel       <<<G1A_BLOCKS * 17, 128>>>(ei, x, W1);  // count ∥ GEMM1-A
    scan_reduce_kernel<<<NBLK_SCAN, 256>>>();
    scan_dist_kernel  <<<NBLK_SCAN, 1024>>>();
    fat2_kernel       <<<(G1B_BLOCKS + 1) * 17, 128>>>(ei, x, W1); // fill ∥ GEMM1-B
    agg1_kernel       <<<(N_NODES + 3) / 4, 128>>>(b1);
    gemm2_kernel      <<<(N_NODES + 255) / 256, 256>>>(W2);
    agg2_kernel       <<<(N_NODES + 7) / 8, 256>>>(b2, out);
}